// round 7
// baseline (speedup 1.0000x reference)
#include <cuda_runtime.h>
#include <cuda_bf16.h>
#include <cstdint>
#include <cstddef>

// ============================================================
// ExpanderLinear: y = x @ W^T + bias
//   x: [N_TOK, 1024] fp32; W: 1024x1024 dense-scattered from 65536 nnz
// Dense tf32 GEMM via legacy mma.sync.
// R6: 3-stage cp.async pipeline (wait_group 1) + ldmatrix.x4 fragment
// loads. R5 profile: tensor=54.9%, L2/DRAM low, occ 24% -> exposed
// tile-load latency; hide it with deeper pipeline + fewer LDS issues.
// ============================================================
#define INDIM   1024
#define OUTDIM  1024

#define BM 128
#define BN 128
#define BK 32
#define KTILES (INDIM / BK)        // 32
#define THREADS 256
#define NSTAGE 3

#define LDSF 36                    // padded row stride in floats
#define A_FLOATS (BM * LDSF)       // 4608
#define B_FLOATS (BN * LDSF)       // 4608
#define STAGE_FLOATS (A_FLOATS + B_FLOATS)       // 9216
#define STAGE_BYTES (STAGE_FLOATS * 4)           // 36864
#define SMEM_BYTES (NSTAGE * STAGE_BYTES)        // 110592 (x2 CTAs = 221KB/SM)

__device__ float g_W[OUTDIM * INDIM];            // 4 MB dense weight (tf32 RN values)
__device__ int   g_is64;                         // edge_index dtype flag

// ============================================================
// Helpers
// ============================================================
__device__ __forceinline__ float tf32_rn(float x) {
    uint32_t u;
    asm("cvt.rn.tf32.f32 %0, %1;" : "=r"(u) : "f"(x));
    return __uint_as_float(u);
}
__device__ __forceinline__ uint32_t smem_u32(const void* p) {
    uint32_t a;
    asm("{ .reg .u64 t; cvta.to.shared.u64 t, %1; cvt.u32.u64 %0, t; }" : "=r"(a) : "l"(p));
    return a;
}
__device__ __forceinline__ void cp_async16(uint32_t dst, const void* src) {
    asm volatile("cp.async.cg.shared.global [%0], [%1], 16;" :: "r"(dst), "l"(src));
}
// zero-fill variant: reads sz bytes (0 or 16), zero-fills the rest
__device__ __forceinline__ void cp_async16z(uint32_t dst, const void* src, unsigned sz) {
    asm volatile("cp.async.cg.shared.global [%0], [%1], 16, %2;" :: "r"(dst), "l"(src), "r"(sz));
}
#define CP_COMMIT() asm volatile("cp.async.commit_group;" ::: "memory")
#define CP_WAIT0()  asm volatile("cp.async.wait_group 0;" ::: "memory")
#define CP_WAIT1()  asm volatile("cp.async.wait_group 1;" ::: "memory")

__device__ __forceinline__ void ldsm4(uint32_t& r0, uint32_t& r1, uint32_t& r2,
                                      uint32_t& r3, uint32_t addr) {
    asm volatile("ldmatrix.sync.aligned.m8n8.x4.shared.b16 {%0,%1,%2,%3}, [%4];"
        : "=r"(r0), "=r"(r1), "=r"(r2), "=r"(r3) : "r"(addr));
}

__device__ __forceinline__ void mma_tf32(float* d, const uint32_t* a, const uint32_t* b) {
    asm volatile(
        "mma.sync.aligned.m16n8k8.row.col.f32.tf32.tf32.f32 "
        "{%0,%1,%2,%3}, {%4,%5,%6,%7}, {%8,%9}, {%0,%1,%2,%3};"
        : "+f"(d[0]), "+f"(d[1]), "+f"(d[2]), "+f"(d[3])
        : "r"(a[0]), "r"(a[1]), "r"(a[2]), "r"(a[3]), "r"(b[0]), "r"(b[1]));
}

// ============================================================
// Prep kernels: zero W in two halves (keeps GEMM at launch #4);
// prep1 also detects the edge_index dtype.
// ============================================================
__global__ void prep0_kernel() {
    int i = blockIdx.x * 256 + threadIdx.x;
    reinterpret_cast<float4*>(g_W)[i] = make_float4(0.f, 0.f, 0.f, 0.f);
}

__global__ void prep1_kernel(const int* __restrict__ ei) {
    int i = blockIdx.x * 256 + threadIdx.x + (OUTDIM * INDIM / 8);
    reinterpret_cast<float4*>(g_W)[i] = make_float4(0.f, 0.f, 0.f, 0.f);
    if (blockIdx.x == 0) {
        // If edge_index is int64, values < 1024 => every odd 32-bit word is 0.
        __shared__ int allzero;
        if (threadIdx.x == 0) allzero = 1;
        __syncthreads();
        if (ei[threadIdx.x * 2 + 1] != 0) allzero = 0;
        __syncthreads();
        if (threadIdx.x == 0) g_is64 = allzero;
    }
}

__global__ void scatter_kernel(const int* __restrict__ ei,
                               const float* __restrict__ val, int nnz) {
    int i = blockIdx.x * 256 + threadIdx.x;
    if (i >= nnz) return;
    int r, c;
    if (g_is64) {
        const long long* e = (const long long*)ei;
        r = (int)e[i];
        c = (int)e[nnz + i];
    } else {
        r = ei[i];
        c = ei[nnz + i];
    }
    atomicAdd(&g_W[r * INDIM + c], tf32_rn(val[i]));
}

// ============================================================
// GEMM: out[m, n] = sum_k X[m,k] * W[n,k] + bias[n]
// BM=128 x BN=128 x BK=32, 8 warps in 2(m) x 4(n), warp tile 64x32.
// 3-stage cp.async pipeline + ldmatrix fragments.
// ============================================================
__global__ void __launch_bounds__(THREADS, 2)
gemm_kernel(const float* __restrict__ x, const float* __restrict__ bias,
            float* __restrict__ out, int n_tok) {
    extern __shared__ float smem[];
    uint32_t sbase = smem_u32(smem);

    const int tid  = threadIdx.x;
    const int wid  = tid >> 5;
    const int lane = tid & 31;
    const int g    = lane >> 2;    // group id 0..7
    const int t    = lane & 3;     // thread in group 0..3

    const int n0 = (blockIdx.x & 7) * BN;   // n fastest -> A-tile L2 reuse
    const int m0 = (blockIdx.x >> 3) * BM;

    const int wm = (wid & 1) * 64;          // warp m-offset in tile
    const int wn = (wid >> 1) * 32;         // warp n-offset in tile

    // ldmatrix per-lane address offsets (within a stage)
    const uint32_t a_lane = (uint32_t)(wm + (lane & 15)) * (LDSF * 4) + (lane >> 4) * 16;
    const uint32_t b_lane = (uint32_t)(wn + (lane & 15)) * (LDSF * 4) + (lane >> 4) * 16
                            + A_FLOATS * 4;

    // ---- stage loader: A [128 x 32] from x (zfill OOB rows) + B [128 x 32] from g_W ----
    auto load_stage = [&](int s, int kc) {
        const int k0 = kc * BK;
        uint32_t dstA = sbase + s * STAGE_BYTES;
        uint32_t dstB = dstA + A_FLOATS * 4;
        #pragma unroll
        for (int it = 0; it < 4; it++) {              // 1024 chunks of 16B (A)
            int ch = tid + it * THREADS;
            int m = ch >> 3, c = ch & 7;
            int row = m0 + m;
            unsigned sz = (row < n_tok) ? 16u : 0u;
            cp_async16z(dstA + m * (LDSF * 4) + c * 16,
                        x + (size_t)row * INDIM + k0 + c * 4, sz);
        }
        #pragma unroll
        for (int it = 0; it < 4; it++) {              // 1024 chunks of 16B (B)
            int ch = tid + it * THREADS;
            int n = ch >> 3, c = ch & 7;
            cp_async16(dstB + n * (LDSF * 4) + c * 16,
                       &g_W[(n0 + n) * INDIM + k0 + c * 4]);
        }
        CP_COMMIT();
    };

    float acc[4][4][4];
    #pragma unroll
    for (int i = 0; i < 4; i++)
        #pragma unroll
        for (int j = 0; j < 4; j++)
            #pragma unroll
            for (int r = 0; r < 4; r++) acc[i][j][r] = 0.f;

    uint32_t afrag[2][4][4];
    uint32_t bfrag[2][4][2];

    load_stage(0, 0);
    load_stage(1, 1);

    for (int kc = 0; kc < KTILES; kc++) {
        const int st = kc % NSTAGE;
        if (kc + 2 < KTILES) { CP_WAIT1(); } else { CP_WAIT0(); }
        __syncthreads();            // stage(kc) visible to all warps
        if (kc + 2 < KTILES) load_stage((kc + 2) % NSTAGE, kc + 2);

        const uint32_t aaddr = sbase + st * STAGE_BYTES + a_lane;
        const uint32_t baddr = sbase + st * STAGE_BYTES + b_lane;

        // fragment loader for one k-slice (8 k) into buffer fb
        auto load_frag = [&](int ks, int fb) {
            #pragma unroll
            for (int tm = 0; tm < 4; tm++)
                ldsm4(afrag[fb][tm][0], afrag[fb][tm][1],
                      afrag[fb][tm][2], afrag[fb][tm][3],
                      aaddr + tm * (16 * LDSF * 4) + ks * 32);
            #pragma unroll
            for (int tnp = 0; tnp < 2; tnp++) {
                uint32_t r0, r1, r2, r3;
                ldsm4(r0, r1, r2, r3, baddr + tnp * (16 * LDSF * 4) + ks * 32);
                bfrag[fb][2 * tnp][0]     = r0;
                bfrag[fb][2 * tnp + 1][0] = r1;
                bfrag[fb][2 * tnp][1]     = r2;
                bfrag[fb][2 * tnp + 1][1] = r3;
            }
        };

        load_frag(0, 0);
        #pragma unroll
        for (int ks = 0; ks < 4; ks++) {
            const int cur = ks & 1;
            if (ks < 3) load_frag(ks + 1, cur ^ 1);   // hide LDSM under MMAs
            #pragma unroll
            for (int tm = 0; tm < 4; tm++)
                #pragma unroll
                for (int tn = 0; tn < 4; tn++)
                    mma_tf32(acc[tm][tn], afrag[cur][tm], bfrag[cur][tn]);
        }
    }

    // ---- epilogue: add bias, store (float2 per row-piece) ----
    #pragma unroll
    for (int tn = 0; tn < 4; tn++) {
        const int c = n0 + wn + tn * 8 + 2 * t;
        const float bv0 = bias[c];
        const float bv1 = bias[c + 1];
        #pragma unroll
        for (int tm = 0; tm < 4; tm++) {
            const int r0 = m0 + wm + tm * 16 + g;
            const int r1 = r0 + 8;
            if (r0 < n_tok) {
                float2 v = make_float2(acc[tm][tn][0] + bv0, acc[tm][tn][1] + bv1);
                *reinterpret_cast<float2*>(&out[(size_t)r0 * OUTDIM + c]) = v;
            }
            if (r1 < n_tok) {
                float2 v = make_float2(acc[tm][tn][2] + bv0, acc[tm][tn][3] + bv1);
                *reinterpret_cast<float2*>(&out[(size_t)r1 * OUTDIM + c]) = v;
            }
        }
    }
}

// ============================================================
// Launch: 4 kernels per call (prep0, prep1, scatter, gemm)
// -> gemm is launch #4 (the one ncu captures)
// ============================================================
extern "C" void kernel_launch(void* const* d_in, const int* in_sizes, int n_in,
                              void* d_out, int out_size) {
    const float* x    = (const float*)d_in[0];
    const float* wval = (const float*)d_in[1];
    const float* bias = (const float*)d_in[2];
    const int*   ei   = (const int*)d_in[3];   // int32 or int64 (detected)

    int n_tok = in_sizes[0] / INDIM;           // 50000
    int nnz   = in_sizes[1];                   // 65536
    float* out = (float*)d_out;

    // 1+2. zero W (two halves; #2 also detects dtype)
    prep0_kernel<<<(OUTDIM * INDIM / 8) / 256, 256>>>();
    prep1_kernel<<<(OUTDIM * INDIM / 8) / 256, 256>>>(ei);
    // 3. scatter tf32-rounded values
    scatter_kernel<<<(nnz + 255) / 256, 256>>>(ei, wval, nnz);
    // 4. tf32 mma.sync GEMM
    int mtiles = (n_tok + BM - 1) / BM;        // 391
    cudaFuncSetAttribute(gemm_kernel, cudaFuncAttributeMaxDynamicSharedMemorySize, SMEM_BYTES);
    gemm_kernel<<<mtiles * (OUTDIM / BN), THREADS, SMEM_BYTES>>>(x, bias, out, n_tok);
}